// round 9
// baseline (speedup 1.0000x reference)
#include <cuda_runtime.h>
#include <cstdint>
#include <cstddef>

#define N_TOK 4096
#define HDIM  1024
#define NE    8
#define CAP   1536

// ---------------- scratch (static device globals: no allocation) ----------------
__device__ float g_hi[(size_t)N_TOK * 512];    // importance hidden
__device__ float g_hr[(size_t)N_TOK * 1024];   // selected-router hidden
__device__ float g_p0[N_TOK], g_p1[N_TOK];
__device__ int   g_e0[N_TOK], g_e1[N_TOK];
__device__ unsigned char g_mask[N_TOK];
__device__ int   g_idx_i[N_TOK], g_idx_u[N_TOK];
__device__ int   g_cnt[2];
__device__ float g_part[512 * 16];

// zeroing split: output region 25,165,824 float4 total
#define ZA_F4 18874368                 // 302 MB zeroed inside gemmA wave (168 zero CTAs)
#define ZC_F4 (25165824 - ZA_F4)       // 100 MB zeroed inside gemmC wave (>=16 zero CTAs)

// ---------------- packed f32x2 helpers ----------------
static __device__ __forceinline__ void fma2(unsigned long long& d,
                                            unsigned long long a,
                                            unsigned long long b) {
    asm("fma.rn.f32x2 %0, %1, %2, %0;" : "+l"(d) : "l"(a), "l"(b));
}
static __device__ __forceinline__ unsigned long long pack2(float x, float y) {
    unsigned long long r;
    asm("mov.b64 %0, {%1, %2};" : "=l"(r) : "f"(x), "f"(y));
    return r;
}
static __device__ __forceinline__ float2 unpack2(unsigned long long v) {
    float2 r;
    asm("mov.b64 {%0, %1}, %2;" : "=f"(r.x), "=f"(r.y) : "l"(v));
    return r;
}

// ---------------- gemmA: relu(X@wi1 + bi1) -> g_hi, plus zero-ballast CTAs ---------
// Unchanged proven 8x8 microtile, occ 2. 1D grid 296: bx<128 compute; else zero 302MB.
__global__ __launch_bounds__(256, 2)
void gemmA_kernel(const float* __restrict__ x,
                  const float* __restrict__ wi1, const float* __restrict__ bi1,
                  float4* __restrict__ zero_base) {
    const int bx = blockIdx.x;
    if (bx >= 128) {
        const int z = bx - 128;
        const float4 zz = make_float4(0.f, 0.f, 0.f, 0.f);
        for (size_t i = (size_t)z * 256 + threadIdx.x; i < (size_t)ZA_F4; i += (size_t)168 * 256)
            zero_base[i] = zz;
        return;
    }
    __shared__ __align__(16) float As[2][8][128];
    __shared__ __align__(16) float Bs[2][8][128];

    const int ncol0 = (bx & 3) * 128;     // 4 col tiles
    const int m0    = (bx >> 2) * 128;    // 32 row tiles
    const int tid   = threadIdx.x;
    const int arow = tid >> 1,  acol = (tid & 1) * 4;
    const int brow = tid >> 5,  bcol = (tid & 31) * 4;
    const float* Ap = x   + (size_t)(m0 + arow) * HDIM + acol;
    const float* Bp = wi1 + (size_t)brow * 512 + ncol0 + bcol;
    const int trow = (tid >> 4) * 8;
    const int tcol = (tid & 15) * 8;

    float4 a_ld = *(const float4*)Ap;
    float4 b_ld = *(const float4*)Bp;
    As[0][acol + 0][arow] = a_ld.x;
    As[0][acol + 1][arow] = a_ld.y;
    As[0][acol + 2][arow] = a_ld.z;
    As[0][acol + 3][arow] = a_ld.w;
    *(float4*)&Bs[0][brow][bcol] = b_ld;
    __syncthreads();

    unsigned long long acc[8][4];
#pragma unroll
    for (int i = 0; i < 8; i++)
#pragma unroll
        for (int j = 0; j < 4; j++) acc[i][j] = 0ull;

    for (int kt = 0; kt < 128; kt++) {
        const int cur = kt & 1;
        float4 a_n, b_n;
        if (kt < 127) {
            a_n = *(const float4*)(Ap + (kt + 1) * 8);
            b_n = *(const float4*)(Bp + (size_t)(kt + 1) * 8 * 512);
        }
#pragma unroll
        for (int k = 0; k < 8; k++) {
            float4 a0 = *(const float4*)&As[cur][k][trow];
            float4 a1 = *(const float4*)&As[cur][k][trow + 4];
            ulonglong2 bq0 = *(const ulonglong2*)&Bs[cur][k][tcol];
            ulonglong2 bq1 = *(const ulonglong2*)&Bs[cur][k][tcol + 4];
            const unsigned long long bb0 = bq0.x, bb1 = bq0.y, bb2 = bq1.x, bb3 = bq1.y;
            float av[8] = {a0.x, a0.y, a0.z, a0.w, a1.x, a1.y, a1.z, a1.w};
#pragma unroll
            for (int i = 0; i < 8; i++) {
                unsigned long long aa = pack2(av[i], av[i]);
                fma2(acc[i][0], aa, bb0);
                fma2(acc[i][1], aa, bb1);
                fma2(acc[i][2], aa, bb2);
                fma2(acc[i][3], aa, bb3);
            }
        }
        if (kt < 127) {
            const int nxt = cur ^ 1;
            As[nxt][acol + 0][arow] = a_n.x;
            As[nxt][acol + 1][arow] = a_n.y;
            As[nxt][acol + 2][arow] = a_n.z;
            As[nxt][acol + 3][arow] = a_n.w;
            *(float4*)&Bs[nxt][brow][bcol] = b_n;
            __syncthreads();
        }
    }

#pragma unroll
    for (int i = 0; i < 8; i++) {
        float* hr = g_hi + (size_t)(m0 + trow + i) * 512 + ncol0 + tcol;
#pragma unroll
        for (int j = 0; j < 4; j++) {
            float2 v = unpack2(acc[i][j]);
            v.x = fmaxf(v.x + bi1[ncol0 + tcol + 2 * j],     0.0f);
            v.y = fmaxf(v.y + bi1[ncol0 + tcol + 2 * j + 1], 0.0f);
            *(float2*)(hr + 2 * j) = v;
        }
    }
}

// ---------------- importance score + mask (warp per token) -------------------------
__global__ void importance_kernel(const float* __restrict__ wi2, const float* __restrict__ bi2,
                                  float* __restrict__ out_imp) {
    const int gt   = (blockIdx.x * blockDim.x + threadIdx.x) >> 5;
    const int lane = threadIdx.x & 31;
    if (gt >= N_TOK) return;
    const float* hr = g_hi + (size_t)gt * 512;
    float z = 0.0f;
    for (int j = lane; j < 512; j += 32) z = fmaf(hr[j], wi2[j], z);
#pragma unroll
    for (int off = 16; off > 0; off >>= 1) z += __shfl_xor_sync(0xffffffffu, z, off);
    if (lane == 0) {
        z += bi2[0];
        const float sig = 1.0f / (1.0f + expf(-z));
        out_imp[gt] = sig;
        g_mask[gt] = (sig > 0.5f) ? 1 : 0;
    }
}

// ---------------- compaction: ordered token lists per branch -----------------------
__global__ void compact_kernel() {
    __shared__ int wcnt_i[32], wcnt_u[32], wpre_i[32], wpre_u[32];
    __shared__ int base_i, base_u;
    const int tid = threadIdx.x, lane = tid & 31, warp = tid >> 5;
    if (tid == 0) { base_i = 0; base_u = 0; }
    __syncthreads();
    for (int c = 0; c < 4; c++) {
        const int t = c * 1024 + tid;
        const int m = g_mask[t];
        const unsigned bi = __ballot_sync(0xffffffffu, m);
        const unsigned lt = (1u << lane) - 1u;
        if (lane == 0) { wcnt_i[warp] = __popc(bi); wcnt_u[warp] = 32 - __popc(bi); }
        __syncthreads();
        if (tid == 0) {
            int si = base_i, su = base_u;
            for (int w = 0; w < 32; w++) {
                wpre_i[w] = si; si += wcnt_i[w];
                wpre_u[w] = su; su += wcnt_u[w];
            }
            base_i = si; base_u = su;
        }
        __syncthreads();
        if (m) g_idx_i[wpre_i[warp] + __popc(bi & lt)] = t;
        else   g_idx_u[wpre_u[warp] + __popc(~bi & lt)] = t;
        __syncthreads();
    }
    if (tid == 0) { g_cnt[0] = base_i; g_cnt[1] = base_u; }
}

// ---------------- gemmC: gathered router GEMM, 8x16 microtile, occ 1 ---------------
// CTA tile 128 x 256, BK=8, 256 threads (16x16), thread tile 8 rows x 16 cols.
// Thread cols: tx*4 + 64*q (q=0..3) -> smem B conflicts capped at degree 2.
// 1D grid 148: bid < 4*nc compute (col tile = bid&3, row tile = bid>>2); rest zero.
__global__ __launch_bounds__(256, 1)
void gemmC_kernel(const float* __restrict__ x,
                  const float* __restrict__ wr1, const float* __restrict__ br1,
                  const float* __restrict__ wu1, const float* __restrict__ bu1,
                  float4* __restrict__ zero_base) {
    const int ci = g_cnt[0], cu = g_cnt[1];
    const int ti = (ci + 127) >> 7;
    const int tu = (cu + 127) >> 7;
    const int nc = ti + tu;                       // 32 or 33 row tiles
    const int bid = blockIdx.x;
    if (bid >= 4 * nc) {
        const int z  = bid - 4 * nc;
        const int nz = 148 - 4 * nc;              // 16 or 20 zero CTAs
        const float4 zz = make_float4(0.f, 0.f, 0.f, 0.f);
        for (size_t i = (size_t)z * 256 + threadIdx.x; i < (size_t)ZC_F4; i += (size_t)nz * 256)
            zero_base[(size_t)ZA_F4 + i] = zz;
        return;
    }
    const int rt = bid >> 2;
    const float* W; const float* bias; const int* list; int base, cnt;
    if (rt < ti) { W = wr1; bias = br1; list = g_idx_i; base = rt << 7;        cnt = ci; }
    else         { W = wu1; bias = bu1; list = g_idx_u; base = (rt - ti) << 7; cnt = cu; }

    __shared__ __align__(16) float As[2][8][128];
    __shared__ __align__(16) float Bs[2][8][256];
    __shared__ int s_tok[128];

    const int ncol0 = (bid & 3) * 256;
    const int tid   = threadIdx.x;
    if (tid < 128) {
        const int r = base + tid;
        s_tok[tid] = (r < cnt) ? list[r] : -1;
    }
    __syncthreads();

    // loaders: A = 1 float4/thread (transposed scatter); B = 2 float4/thread
    const int arow = tid >> 1,  acol = (tid & 1) * 4;
    const int brow = tid >> 5,  bcol = (tid & 31) * 4;
    const int tokA = s_tok[arow];
    const float* Ap = x + (size_t)(tokA < 0 ? 0 : tokA) * HDIM + acol;
    const float* Bp = W + (size_t)brow * 1024 + ncol0 + bcol;

    // compute mapping: ty rows [ty*8, +8), tx cols {tx*4 + 64q}
    const int ty = tid >> 4, tx = tid & 15;
    const int trow = ty * 8;
    const int tcol = tx * 4;

    float4 a_ld = *(const float4*)Ap;
    float4 b_ld0 = *(const float4*)Bp;
    float4 b_ld1 = *(const float4*)(Bp + 128);
    As[0][acol + 0][arow] = a_ld.x;
    As[0][acol + 1][arow] = a_ld.y;
    As[0][acol + 2][arow] = a_ld.z;
    As[0][acol + 3][arow] = a_ld.w;
    *(float4*)&Bs[0][brow][bcol]       = b_ld0;
    *(float4*)&Bs[0][brow][bcol + 128] = b_ld1;
    __syncthreads();

    unsigned long long acc[8][4][2];
#pragma unroll
    for (int i = 0; i < 8; i++)
#pragma unroll
        for (int q = 0; q < 4; q++) { acc[i][q][0] = 0ull; acc[i][q][1] = 0ull; }

    for (int kt = 0; kt < 128; kt++) {
        const int cur = kt & 1;
        float4 a_n, b_n0, b_n1;
        if (kt < 127) {
            a_n  = *(const float4*)(Ap + (kt + 1) * 8);
            b_n0 = *(const float4*)(Bp + (size_t)(kt + 1) * 8 * 1024);
            b_n1 = *(const float4*)(Bp + (size_t)(kt + 1) * 8 * 1024 + 128);
        }
#pragma unroll
        for (int k = 0; k < 8; k++) {
            float4 a0 = *(const float4*)&As[cur][k][trow];
            float4 a1 = *(const float4*)&As[cur][k][trow + 4];
            ulonglong2 b0 = *(const ulonglong2*)&Bs[cur][k][tcol];
            ulonglong2 b1 = *(const ulonglong2*)&Bs[cur][k][tcol + 64];
            ulonglong2 b2 = *(const ulonglong2*)&Bs[cur][k][tcol + 128];
            ulonglong2 b3 = *(const ulonglong2*)&Bs[cur][k][tcol + 192];
            float av[8] = {a0.x, a0.y, a0.z, a0.w, a1.x, a1.y, a1.z, a1.w};
#pragma unroll
            for (int i = 0; i < 8; i++) {
                unsigned long long aa = pack2(av[i], av[i]);
                fma2(acc[i][0][0], aa, b0.x);
                fma2(acc[i][0][1], aa, b0.y);
                fma2(acc[i][1][0], aa, b1.x);
                fma2(acc[i][1][1], aa, b1.y);
                fma2(acc[i][2][0], aa, b2.x);
                fma2(acc[i][2][1], aa, b2.y);
                fma2(acc[i][3][0], aa, b3.x);
                fma2(acc[i][3][1], aa, b3.y);
            }
        }
        if (kt < 127) {
            const int nxt = cur ^ 1;
            As[nxt][acol + 0][arow] = a_n.x;
            As[nxt][acol + 1][arow] = a_n.y;
            As[nxt][acol + 2][arow] = a_n.z;
            As[nxt][acol + 3][arow] = a_n.w;
            *(float4*)&Bs[nxt][brow][bcol]       = b_n0;
            *(float4*)&Bs[nxt][brow][bcol + 128] = b_n1;
            __syncthreads();
        }
    }

    // epilogue: bias + relu, float4 stores at cols ncol0 + tx*4 + 64q
#pragma unroll
    for (int i = 0; i < 8; i++) {
        const int tok = s_tok[trow + i];
        if (tok < 0) continue;
        float* hr = g_hr + (size_t)tok * 1024 + ncol0;
#pragma unroll
        for (int q = 0; q < 4; q++) {
            const int col = tcol + 64 * q;
            const float4 bs = *(const float4*)(bias + ncol0 + col);
            float2 v0 = unpack2(acc[i][q][0]);
            float2 v1 = unpack2(acc[i][q][1]);
            float4 v;
            v.x = fmaxf(v0.x + bs.x, 0.0f);
            v.y = fmaxf(v0.y + bs.y, 0.0f);
            v.z = fmaxf(v1.x + bs.z, 0.0f);
            v.w = fmaxf(v1.y + bs.w, 0.0f);
            *(float4*)(hr + col) = v;
        }
    }
}

// ---------------- routing: second layer + softmax + top-2 + aux partials -----------
__global__ void routing_kernel(const float* __restrict__ wr2, const float* __restrict__ br2,
                               const float* __restrict__ wu2, const float* __restrict__ bu2,
                               float* __restrict__ out_probs) {
    __shared__ float s_aux[8][16];
    const int gt   = (blockIdx.x * blockDim.x + threadIdx.x) >> 5;
    const int lane = threadIdx.x & 31;
    const int warp = threadIdx.x >> 5;
    if (gt < N_TOK) {
        const bool m = g_mask[gt] != 0;
        const float* hs = g_hr + (size_t)gt * 1024;
        const float* W2 = m ? wr2 : wu2;
        const float* b2 = m ? br2 : bu2;
        float acc[NE];
#pragma unroll
        for (int e = 0; e < NE; e++) acc[e] = 0.0f;
        for (int j = lane; j < 1024; j += 32) {
            const float hv = hs[j];
            float4 w0 = *(const float4*)(W2 + (size_t)j * 8);
            float4 w1 = *(const float4*)(W2 + (size_t)j * 8 + 4);
            acc[0] = fmaf(hv, w0.x, acc[0]);
            acc[1] = fmaf(hv, w0.y, acc[1]);
            acc[2] = fmaf(hv, w0.z, acc[2]);
            acc[3] = fmaf(hv, w0.w, acc[3]);
            acc[4] = fmaf(hv, w1.x, acc[4]);
            acc[5] = fmaf(hv, w1.y, acc[5]);
            acc[6] = fmaf(hv, w1.z, acc[6]);
            acc[7] = fmaf(hv, w1.w, acc[7]);
        }
#pragma unroll
        for (int off = 16; off > 0; off >>= 1)
#pragma unroll
            for (int e = 0; e < NE; e++) acc[e] += __shfl_xor_sync(0xffffffffu, acc[e], off);

        if (lane == 0) {
            float l[NE], pr[NE];
            float mx = -1e30f;
#pragma unroll
            for (int e = 0; e < NE; e++) { l[e] = acc[e] + b2[e]; mx = fmaxf(mx, l[e]); }
            float sum = 0.0f;
#pragma unroll
            for (int e = 0; e < NE; e++) { pr[e] = expf(l[e] - mx); sum += pr[e]; }
            const float inv = 1.0f / sum;
            const float mf = m ? 1.0f : 0.0f;
#pragma unroll
            for (int e = 0; e < NE; e++) {
                pr[e] *= inv;
                out_probs[(size_t)gt * NE + e] = pr[e];
                s_aux[warp][e]      = pr[e];
                s_aux[warp][NE + e] = pr[e] * mf;
            }
            int e0 = 0; float p0v = pr[0];
#pragma unroll
            for (int e = 1; e < NE; e++) if (pr[e] > p0v) { p0v = pr[e]; e0 = e; }
            int e1 = -1; float p1v = -1.0f;
#pragma unroll
            for (int e = 0; e < NE; e++) if (e != e0 && pr[e] > p1v) { p1v = pr[e]; e1 = e; }
            const float sn = p0v + p1v;
            g_e0[gt] = e0; g_e1[gt] = e1;
            g_p0[gt] = p0v / sn; g_p1[gt] = p1v / sn;
        }
    }
    __syncthreads();
    if (threadIdx.x < 16) {
        float s = 0.0f;
        for (int w = 0; w < 8; w++) s += s_aux[w][threadIdx.x];
        g_part[(size_t)blockIdx.x * 16 + threadIdx.x] = s;
    }
}

// ---------------- dispatch (block 0) + aux loss (block 1), merged ------------------
__global__ void dispatch_aux_kernel(float* __restrict__ disp, float* __restrict__ comb,
                                    float* __restrict__ out_aux) {
    const int tid = threadIdx.x;
    if (blockIdx.x == 0) {
        __shared__ int base[NE];
        __shared__ int whist[32][NE];
        __shared__ int wpref[32][NE];
        const int lane = tid & 31, warp = tid >> 5;
        if (tid < NE) base[tid] = 0;
        __syncthreads();
        for (int chunk = 0; chunk < 8; chunk++) {
            const int i = chunk * 1024 + tid;
            const int k = i >> 12;
            const int t = i & (N_TOK - 1);
            const int e   = (k == 0) ? g_e0[t] : g_e1[t];
            const float p = (k == 0) ? g_p0[t] : g_p1[t];

            if (lane < NE) whist[warp][lane] = 0;
            __syncwarp();
            const unsigned mm  = __match_any_sync(0xffffffffu, e);
            const unsigned blo = mm & ((1u << lane) - 1u);
            const int rank = __popc(blo);
            if (blo == 0u) whist[warp][e] = __popc(mm);
            __syncthreads();

            if (tid < NE) {
                int s = base[tid];
                for (int w = 0; w < 32; w++) { wpref[w][tid] = s; s += whist[w][tid]; }
                base[tid] = s;
            }
            __syncthreads();

            const int pos = wpref[warp][e] + rank;
            if (pos < CAP) {
                const size_t idx = ((size_t)t * NE + e) * CAP + pos;
                disp[idx] = 1.0f;
                comb[idx] = p;
            }
            __syncthreads();
        }
    } else {
        __shared__ float sm[512][16];
        if (tid < 512) {
#pragma unroll
            for (int v = 0; v < 16; v++) sm[tid][v] = g_part[(size_t)tid * 16 + v];
        }
        __syncthreads();
        for (int s = 256; s > 0; s >>= 1) {
            if (tid < s)
#pragma unroll
                for (int v = 0; v < 16; v++) sm[tid][v] += sm[tid + s][v];
            __syncthreads();
        }
        if (tid == 0) {
            float ent = 0.0f;
#pragma unroll
            for (int e = 0; e < NE; e++) {
                const float r = sm[0][e] / (float)N_TOK;
                ent += r * logf(r * 8.0f + 1e-9f);
            }
            float tot = 0.0f;
            float SI[NE];
#pragma unroll
            for (int e = 0; e < NE; e++) { SI[e] = sm[0][NE + e] + 1e-9f; tot += SI[e]; }
            float ie = 0.0f;
#pragma unroll
            for (int e = 0; e < NE; e++) {
                const float ip = SI[e] / tot;
                ie -= ip * logf(ip + 1e-9f);
            }
            out_aux[0] = ent - 0.1f * (ie / logf(8.0f));
        }
    }
}

// ---------------- launch -----------------------------------------------------------
extern "C" void kernel_launch(void* const* d_in, const int* in_sizes, int n_in,
                              void* d_out, int out_size) {
    const float* x   = (const float*)d_in[0];
    const float* wi1 = (const float*)d_in[1];
    const float* bi1 = (const float*)d_in[2];
    const float* wi2 = (const float*)d_in[3];
    const float* bi2 = (const float*)d_in[4];
    const float* wr1 = (const float*)d_in[5];
    const float* br1 = (const float*)d_in[6];
    const float* wr2 = (const float*)d_in[7];
    const float* br2 = (const float*)d_in[8];
    const float* wu1 = (const float*)d_in[9];
    const float* bu1 = (const float*)d_in[10];
    const float* wu2 = (const float*)d_in[11];
    const float* bu2 = (const float*)d_in[12];

    float* out   = (float*)d_out;
    float* disp  = out;                                   // [4096, 8, 1536]
    float* comb  = disp + (size_t)N_TOK * NE * CAP;       // [4096, 8, 1536]
    float* probs = comb + (size_t)N_TOK * NE * CAP;       // [4096, 8]
    float* aux   = probs + (size_t)N_TOK * NE;            // [1]
    float* imp   = aux + 1;                               // [4096]

    gemmA_kernel<<<296, 256>>>(x, wi1, bi1, (float4*)disp);
    importance_kernel<<<512, 256>>>(wi2, bi2, imp);
    compact_kernel<<<1, 1024>>>();
    gemmC_kernel<<<148, 256>>>(x, wr1, br1, wu1, bu1, (float4*)disp);
    routing_kernel<<<512, 256>>>(wr2, br2, wu2, bu2, probs);
    dispatch_aux_kernel<<<2, 1024>>>(disp, comb, aux);
}

// round 10
// speedup vs baseline: 1.2604x; 1.2604x over previous
#include <cuda_runtime.h>
#include <cstdint>
#include <cstddef>

#define N_TOK 4096
#define HDIM  1024
#define NE    8
#define CAP   1536

// ---------------- scratch (static device globals: no allocation) ----------------
__device__ float g_zpart[(size_t)N_TOK * 4];   // per-token importance dot partials (4 col tiles)
__device__ float g_hr[(size_t)N_TOK * 1024];   // selected-router hidden
__device__ float g_p0[N_TOK], g_p1[N_TOK];
__device__ int   g_e0[N_TOK], g_e1[N_TOK];
__device__ unsigned char g_mask[N_TOK];
__device__ int   g_idx_i[N_TOK], g_idx_u[N_TOK];
__device__ int   g_cnt[2];
__device__ float g_part[512 * 16];

// zeroing split (R8-proven): output region 25,165,824 float4 total
#define ZA_F4 9830400                  // 150 MB zeroed inside gemmA wave (64 zero CTAs)
#define ZC_F4 (25165824 - ZA_F4)       // 252 MB zeroed inside gemmC wave (>=32 zero CTAs)

// ---------------- packed f32x2 helpers ----------------
static __device__ __forceinline__ void fma2(unsigned long long& d,
                                            unsigned long long a,
                                            unsigned long long b) {
    asm("fma.rn.f32x2 %0, %1, %2, %0;" : "+l"(d) : "l"(a), "l"(b));
}
static __device__ __forceinline__ unsigned long long pack2(float x, float y) {
    unsigned long long r;
    asm("mov.b64 %0, {%1, %2};" : "=l"(r) : "f"(x), "f"(y));
    return r;
}
static __device__ __forceinline__ float2 unpack2(unsigned long long v) {
    float2 r;
    asm("mov.b64 {%0, %1}, %2;" : "=f"(r.x), "=f"(r.y) : "l"(v));
    return r;
}

// ---------------- gemmA: X@wi1 + bi1 -> relu -> dot(wi2) partials ------------------
// R8-proven 8x8 microtile, occ 2. 1D grid 192: bx<128 compute; else zero 150MB.
// Epilogue does NOT store hidden; reduces against wi2 into g_zpart[token][ncol0/128].
__global__ __launch_bounds__(256, 2)
void gemmA_kernel(const float* __restrict__ x,
                  const float* __restrict__ wi1, const float* __restrict__ bi1,
                  const float* __restrict__ wi2,
                  float4* __restrict__ zero_base) {
    const int bx = blockIdx.x;
    if (bx >= 128) {
        const int z = bx - 128;
        const float4 zz = make_float4(0.f, 0.f, 0.f, 0.f);
        for (size_t i = (size_t)z * 256 + threadIdx.x; i < (size_t)ZA_F4; i += (size_t)64 * 256)
            zero_base[i] = zz;
        return;
    }
    __shared__ __align__(16) float As[2][8][128];
    __shared__ __align__(16) float Bs[2][8][128];

    const int ncol0 = (bx & 3) * 128;     // 4 col tiles
    const int m0    = (bx >> 2) * 128;    // 32 row tiles
    const int tid   = threadIdx.x;
    const int arow = tid >> 1,  acol = (tid & 1) * 4;
    const int brow = tid >> 5,  bcol = (tid & 31) * 4;
    const float* Ap = x   + (size_t)(m0 + arow) * HDIM + acol;
    const float* Bp = wi1 + (size_t)brow * 512 + ncol0 + bcol;
    const int trow = (tid >> 4) * 8;
    const int tcol = (tid & 15) * 8;

    float4 a_ld = *(const float4*)Ap;
    float4 b_ld = *(const float4*)Bp;
    As[0][acol + 0][arow] = a_ld.x;
    As[0][acol + 1][arow] = a_ld.y;
    As[0][acol + 2][arow] = a_ld.z;
    As[0][acol + 3][arow] = a_ld.w;
    *(float4*)&Bs[0][brow][bcol] = b_ld;
    __syncthreads();

    unsigned long long acc[8][4];
#pragma unroll
    for (int i = 0; i < 8; i++)
#pragma unroll
        for (int j = 0; j < 4; j++) acc[i][j] = 0ull;

    for (int kt = 0; kt < 128; kt++) {
        const int cur = kt & 1;
        float4 a_n, b_n;
        if (kt < 127) {
            a_n = *(const float4*)(Ap + (kt + 1) * 8);
            b_n = *(const float4*)(Bp + (size_t)(kt + 1) * 8 * 512);
        }
#pragma unroll
        for (int k = 0; k < 8; k++) {
            float4 a0 = *(const float4*)&As[cur][k][trow];
            float4 a1 = *(const float4*)&As[cur][k][trow + 4];
            ulonglong2 bq0 = *(const ulonglong2*)&Bs[cur][k][tcol];
            ulonglong2 bq1 = *(const ulonglong2*)&Bs[cur][k][tcol + 4];
            const unsigned long long bb0 = bq0.x, bb1 = bq0.y, bb2 = bq1.x, bb3 = bq1.y;
            float av[8] = {a0.x, a0.y, a0.z, a0.w, a1.x, a1.y, a1.z, a1.w};
#pragma unroll
            for (int i = 0; i < 8; i++) {
                unsigned long long aa = pack2(av[i], av[i]);
                fma2(acc[i][0], aa, bb0);
                fma2(acc[i][1], aa, bb1);
                fma2(acc[i][2], aa, bb2);
                fma2(acc[i][3], aa, bb3);
            }
        }
        if (kt < 127) {
            const int nxt = cur ^ 1;
            As[nxt][acol + 0][arow] = a_n.x;
            As[nxt][acol + 1][arow] = a_n.y;
            As[nxt][acol + 2][arow] = a_n.z;
            As[nxt][acol + 3][arow] = a_n.w;
            *(float4*)&Bs[nxt][brow][bcol] = b_n;
            __syncthreads();
        }
    }

    // ---- epilogue: bias + relu, reduce against wi2, 16-lane shuffle tree ----
    float w[8];
#pragma unroll
    for (int jj = 0; jj < 8; jj++) w[jj] = wi2[ncol0 + tcol + jj];
    float zp[8];
#pragma unroll
    for (int i = 0; i < 8; i++) {
        float s = 0.0f;
#pragma unroll
        for (int j = 0; j < 4; j++) {
            float2 v = unpack2(acc[i][j]);
            v.x = fmaxf(v.x + bi1[ncol0 + tcol + 2 * j],     0.0f);
            v.y = fmaxf(v.y + bi1[ncol0 + tcol + 2 * j + 1], 0.0f);
            s = fmaf(v.x, w[2 * j], s);
            s = fmaf(v.y, w[2 * j + 1], s);
        }
        zp[i] = s;
    }
#pragma unroll
    for (int off = 8; off > 0; off >>= 1)
#pragma unroll
        for (int i = 0; i < 8; i++) zp[i] += __shfl_xor_sync(0xffffffffu, zp[i], off);
    if ((tid & 15) == 0) {
#pragma unroll
        for (int i = 0; i < 8; i++)
            g_zpart[(size_t)(m0 + trow + i) * 4 + (ncol0 >> 7)] = zp[i];
    }
}

// ---------------- gate + compact (fused, single block) -----------------------------
__global__ void gate_compact_kernel(const float* __restrict__ bi2,
                                    float* __restrict__ out_imp) {
    __shared__ int wcnt_i[32], wcnt_u[32], wpre_i[32], wpre_u[32];
    __shared__ int base_i, base_u;
    const int tid = threadIdx.x, lane = tid & 31, warp = tid >> 5;
    if (tid == 0) { base_i = 0; base_u = 0; }
    __syncthreads();
    for (int c = 0; c < 4; c++) {
        const int t = c * 1024 + tid;
        const float4 zp = *(const float4*)&g_zpart[(size_t)t * 4];
        const float z = ((zp.x + zp.y) + zp.z) + zp.w + bi2[0];
        const float sig = 1.0f / (1.0f + expf(-z));
        const int m = (sig > 0.5f) ? 1 : 0;
        out_imp[t] = sig;
        g_mask[t] = (unsigned char)m;

        const unsigned bi = __ballot_sync(0xffffffffu, m);
        const unsigned lt = (1u << lane) - 1u;
        if (lane == 0) { wcnt_i[warp] = __popc(bi); wcnt_u[warp] = 32 - __popc(bi); }
        __syncthreads();
        if (tid == 0) {
            int si = base_i, su = base_u;
            for (int w = 0; w < 32; w++) {
                wpre_i[w] = si; si += wcnt_i[w];
                wpre_u[w] = su; su += wcnt_u[w];
            }
            base_i = si; base_u = su;
        }
        __syncthreads();
        if (m) g_idx_i[wpre_i[warp] + __popc(bi & lt)] = t;
        else   g_idx_u[wpre_u[warp] + __popc(~bi & lt)] = t;
        __syncthreads();
    }
    if (tid == 0) { g_cnt[0] = base_i; g_cnt[1] = base_u; }
}

// ---------------- gemmC: gathered router GEMM + zero-ballast CTAs (R8-proven) ------
__global__ __launch_bounds__(256, 2)
void gemmC_kernel(const float* __restrict__ x,
                  const float* __restrict__ wr1, const float* __restrict__ br1,
                  const float* __restrict__ wu1, const float* __restrict__ bu1,
                  float4* __restrict__ zero_base) {
    const int ci = g_cnt[0], cu = g_cnt[1];
    const int ti = (ci + 127) >> 7;
    const int tu = (cu + 127) >> 7;
    const int nc = ti + tu;                       // 32 or 33 row tiles
    const int bid = blockIdx.x;
    if (bid >= 8 * nc) {
        const int z  = bid - 8 * nc;
        const int nz = 296 - 8 * nc;
        const float4 zz = make_float4(0.f, 0.f, 0.f, 0.f);
        for (size_t i = (size_t)z * 256 + threadIdx.x; i < (size_t)ZC_F4; i += (size_t)nz * 256)
            zero_base[(size_t)ZA_F4 + i] = zz;
        return;
    }
    const int rt = bid >> 3;
    const float* W; const float* bias; const int* list; int base, cnt;
    if (rt < ti) { W = wr1; bias = br1; list = g_idx_i; base = rt << 7;        cnt = ci; }
    else         { W = wu1; bias = bu1; list = g_idx_u; base = (rt - ti) << 7; cnt = cu; }

    __shared__ __align__(16) float As[2][8][128];
    __shared__ __align__(16) float Bs[2][8][128];
    __shared__ int s_tok[128];

    const int ncol0 = (bid & 7) * 128;
    const int tid   = threadIdx.x;
    if (tid < 128) {
        const int r = base + tid;
        s_tok[tid] = (r < cnt) ? list[r] : -1;
    }
    __syncthreads();

    const int arow = tid >> 1,  acol = (tid & 1) * 4;
    const int brow = tid >> 5,  bcol = (tid & 31) * 4;
    const int tokA = s_tok[arow];
    const float* Ap = x + (size_t)(tokA < 0 ? 0 : tokA) * HDIM + acol;
    const float* Bp = W + (size_t)brow * 1024 + ncol0 + bcol;
    const int trow = (tid >> 4) * 8;
    const int tcol = (tid & 15) * 8;

    float4 a_ld = *(const float4*)Ap;
    float4 b_ld = *(const float4*)Bp;
    As[0][acol + 0][arow] = a_ld.x;
    As[0][acol + 1][arow] = a_ld.y;
    As[0][acol + 2][arow] = a_ld.z;
    As[0][acol + 3][arow] = a_ld.w;
    *(float4*)&Bs[0][brow][bcol] = b_ld;
    __syncthreads();

    unsigned long long acc[8][4];
#pragma unroll
    for (int i = 0; i < 8; i++)
#pragma unroll
        for (int j = 0; j < 4; j++) acc[i][j] = 0ull;

    for (int kt = 0; kt < 128; kt++) {
        const int cur = kt & 1;
        float4 a_n, b_n;
        if (kt < 127) {
            a_n = *(const float4*)(Ap + (kt + 1) * 8);
            b_n = *(const float4*)(Bp + (size_t)(kt + 1) * 8 * 1024);
        }
#pragma unroll
        for (int k = 0; k < 8; k++) {
            float4 a0 = *(const float4*)&As[cur][k][trow];
            float4 a1 = *(const float4*)&As[cur][k][trow + 4];
            ulonglong2 bq0 = *(const ulonglong2*)&Bs[cur][k][tcol];
            ulonglong2 bq1 = *(const ulonglong2*)&Bs[cur][k][tcol + 4];
            const unsigned long long bb0 = bq0.x, bb1 = bq0.y, bb2 = bq1.x, bb3 = bq1.y;
            float av[8] = {a0.x, a0.y, a0.z, a0.w, a1.x, a1.y, a1.z, a1.w};
#pragma unroll
            for (int i = 0; i < 8; i++) {
                unsigned long long aa = pack2(av[i], av[i]);
                fma2(acc[i][0], aa, bb0);
                fma2(acc[i][1], aa, bb1);
                fma2(acc[i][2], aa, bb2);
                fma2(acc[i][3], aa, bb3);
            }
        }
        if (kt < 127) {
            const int nxt = cur ^ 1;
            As[nxt][acol + 0][arow] = a_n.x;
            As[nxt][acol + 1][arow] = a_n.y;
            As[nxt][acol + 2][arow] = a_n.z;
            As[nxt][acol + 3][arow] = a_n.w;
            *(float4*)&Bs[nxt][brow][bcol] = b_n;
            __syncthreads();
        }
    }

#pragma unroll
    for (int i = 0; i < 8; i++) {
        const int tok = s_tok[trow + i];
        if (tok < 0) continue;
        float* hr = g_hr + (size_t)tok * 1024 + ncol0 + tcol;
#pragma unroll
        for (int j = 0; j < 4; j++) {
            float2 v = unpack2(acc[i][j]);
            v.x = fmaxf(v.x + bias[ncol0 + tcol + 2 * j],     0.0f);
            v.y = fmaxf(v.y + bias[ncol0 + tcol + 2 * j + 1], 0.0f);
            *(float2*)(hr + 2 * j) = v;
        }
    }
}

// ---------------- routing: second layer + softmax + top-2 + aux partials -----------
__global__ void routing_kernel(const float* __restrict__ wr2, const float* __restrict__ br2,
                               const float* __restrict__ wu2, const float* __restrict__ bu2,
                               float* __restrict__ out_probs) {
    __shared__ float s_aux[8][16];
    const int gt   = (blockIdx.x * blockDim.x + threadIdx.x) >> 5;
    const int lane = threadIdx.x & 31;
    const int warp = threadIdx.x >> 5;
    if (gt < N_TOK) {
        const bool m = g_mask[gt] != 0;
        const float* hs = g_hr + (size_t)gt * 1024;
        const float* W2 = m ? wr2 : wu2;
        const float* b2 = m ? br2 : bu2;
        float acc[NE];
#pragma unroll
        for (int e = 0; e < NE; e++) acc[e] = 0.0f;
        for (int j = lane; j < 1024; j += 32) {
            const float hv = hs[j];
            float4 w0 = *(const float4*)(W2 + (size_t)j * 8);
            float4 w1 = *(const float4*)(W2 + (size_t)j * 8 + 4);
            acc[0] = fmaf(hv, w0.x, acc[0]);
            acc[1] = fmaf(hv, w0.y, acc[1]);
            acc[2] = fmaf(hv, w0.z, acc[2]);
            acc[3] = fmaf(hv, w0.w, acc[3]);
            acc[4] = fmaf(hv, w1.x, acc[4]);
            acc[5] = fmaf(hv, w1.y, acc[5]);
            acc[6] = fmaf(hv, w1.z, acc[6]);
            acc[7] = fmaf(hv, w1.w, acc[7]);
        }
#pragma unroll
        for (int off = 16; off > 0; off >>= 1)
#pragma unroll
            for (int e = 0; e < NE; e++) acc[e] += __shfl_xor_sync(0xffffffffu, acc[e], off);

        if (lane == 0) {
            float l[NE], pr[NE];
            float mx = -1e30f;
#pragma unroll
            for (int e = 0; e < NE; e++) { l[e] = acc[e] + b2[e]; mx = fmaxf(mx, l[e]); }
            float sum = 0.0f;
#pragma unroll
            for (int e = 0; e < NE; e++) { pr[e] = expf(l[e] - mx); sum += pr[e]; }
            const float inv = 1.0f / sum;
            const float mf = m ? 1.0f : 0.0f;
#pragma unroll
            for (int e = 0; e < NE; e++) {
                pr[e] *= inv;
                out_probs[(size_t)gt * NE + e] = pr[e];
                s_aux[warp][e]      = pr[e];
                s_aux[warp][NE + e] = pr[e] * mf;
            }
            int e0 = 0; float p0v = pr[0];
#pragma unroll
            for (int e = 1; e < NE; e++) if (pr[e] > p0v) { p0v = pr[e]; e0 = e; }
            int e1 = -1; float p1v = -1.0f;
#pragma unroll
            for (int e = 0; e < NE; e++) if (e != e0 && pr[e] > p1v) { p1v = pr[e]; e1 = e; }
            const float sn = p0v + p1v;
            g_e0[gt] = e0; g_e1[gt] = e1;
            g_p0[gt] = p0v / sn; g_p1[gt] = p1v / sn;
        }
    }
    __syncthreads();
    if (threadIdx.x < 16) {
        float s = 0.0f;
        for (int w = 0; w < 8; w++) s += s_aux[w][threadIdx.x];
        g_part[(size_t)blockIdx.x * 16 + threadIdx.x] = s;
    }
}

// ---------------- dispatch (block 0) + aux loss (block 1), merged ------------------
__global__ void dispatch_aux_kernel(float* __restrict__ disp, float* __restrict__ comb,
                                    float* __restrict__ out_aux) {
    const int tid = threadIdx.x;
    if (blockIdx.x == 0) {
        __shared__ int base[NE];
        __shared__ int whist[32][NE];
        __shared__ int wpref[32][NE];
        const int lane = tid & 31, warp = tid >> 5;
        if (tid < NE) base[tid] = 0;
        __syncthreads();
        for (int chunk = 0; chunk < 8; chunk++) {
            const int i = chunk * 1024 + tid;
            const int k = i >> 12;
            const int t = i & (N_TOK - 1);
            const int e   = (k == 0) ? g_e0[t] : g_e1[t];
            const float p = (k == 0) ? g_p0[t] : g_p1[t];

            if (lane < NE) whist[warp][lane] = 0;
            __syncwarp();
            const unsigned mm  = __match_any_sync(0xffffffffu, e);
            const unsigned blo = mm & ((1u << lane) - 1u);
            const int rank = __popc(blo);
            if (blo == 0u) whist[warp][e] = __popc(mm);
            __syncthreads();

            if (tid < NE) {
                int s = base[tid];
                for (int w = 0; w < 32; w++) { wpref[w][tid] = s; s += whist[w][tid]; }
                base[tid] = s;
            }
            __syncthreads();

            const int pos = wpref[warp][e] + rank;
            if (pos < CAP) {
                const size_t idx = ((size_t)t * NE + e) * CAP + pos;
                disp[idx] = 1.0f;
                comb[idx] = p;
            }
            __syncthreads();
        }
    } else {
        __shared__ float sm[512][16];
        if (tid < 512) {
#pragma unroll
            for (int v = 0; v < 16; v++) sm[tid][v] = g_part[(size_t)tid * 16 + v];
        }
        __syncthreads();
        for (int s = 256; s > 0; s >>= 1) {
            if (tid < s)
#pragma unroll
                for (int v = 0; v < 16; v++) sm[tid][v] += sm[tid + s][v];
            __syncthreads();
        }
        if (tid == 0) {
            float ent = 0.0f;
#pragma unroll
            for (int e = 0; e < NE; e++) {
                const float r = sm[0][e] / (float)N_TOK;
                ent += r * logf(r * 8.0f + 1e-9f);
            }
            float tot = 0.0f;
            float SI[NE];
#pragma unroll
            for (int e = 0; e < NE; e++) { SI[e] = sm[0][NE + e] + 1e-9f; tot += SI[e]; }
            float ie = 0.0f;
#pragma unroll
            for (int e = 0; e < NE; e++) {
                const float ip = SI[e] / tot;
                ie -= ip * logf(ip + 1e-9f);
            }
            out_aux[0] = ent - 0.1f * (ie / logf(8.0f));
        }
    }
}

// ---------------- launch -----------------------------------------------------------
extern "C" void kernel_launch(void* const* d_in, const int* in_sizes, int n_in,
                              void* d_out, int out_size) {
    const float* x   = (const float*)d_in[0];
    const float* wi1 = (const float*)d_in[1];
    const float* bi1 = (const float*)d_in[2];
    const float* wi2 = (const float*)d_in[3];
    const float* bi2 = (const float*)d_in[4];
    const float* wr1 = (const float*)d_in[5];
    const float* br1 = (const float*)d_in[6];
    const float* wr2 = (const float*)d_in[7];
    const float* br2 = (const float*)d_in[8];
    const float* wu1 = (const float*)d_in[9];
    const float* bu1 = (const float*)d_in[10];
    const float* wu2 = (const float*)d_in[11];
    const float* bu2 = (const float*)d_in[12];

    float* out   = (float*)d_out;
    float* disp  = out;                                   // [4096, 8, 1536]
    float* comb  = disp + (size_t)N_TOK * NE * CAP;       // [4096, 8, 1536]
    float* probs = comb + (size_t)N_TOK * NE * CAP;       // [4096, 8]
    float* aux   = probs + (size_t)N_TOK * NE;            // [1]
    float* imp   = aux + 1;                               // [4096]

    gemmA_kernel<<<192, 256>>>(x, wi1, bi1, wi2, (float4*)disp);
    gate_compact_kernel<<<1, 1024>>>(bi2, imp);
    gemmC_kernel<<<296, 256>>>(x, wr1, br1, wu1, bu1, (float4*)disp);
    routing_kernel<<<512, 256>>>(wr2, br2, wu2, bu2, probs);
    dispatch_aux_kernel<<<2, 1024>>>(disp, comb, aux);
}